// round 14
// baseline (speedup 1.0000x reference)
#include <cuda_runtime.h>
#include <cuda_bf16.h>
#include <cstdint>

#define BATCH   65536
#define SLEN    128
#define NCLS    10
#define SD      14
#define D       256
#define TM      128     // tasks per block (GEMM M)
#define THREADS 512

// w2 tf32 bits, packed in mma.m16n8k8 B-fragment order:
// uint32 index = ((ks*8 + wc)*32 + lane)*8 + j*2 + r
__device__ __align__(16) uint32_t g_w2f[32 * 8 * 32 * 8];

#define BSTRIDE_U4 512   // uint4 elements per ks step

__device__ __forceinline__ uint32_t s2u(const void* p) {
    return (uint32_t)__cvta_generic_to_shared(p);
}

__device__ __forceinline__ uint32_t f2tf32(float x) {
    uint32_t r;
    asm("cvt.rna.tf32.f32 %0, %1;" : "=r"(r) : "f"(x));
    return r;
}

__device__ __forceinline__ void mma_tf32(float* c, const uint32_t* a, uint32_t b0, uint32_t b1) {
    asm volatile(
        "mma.sync.aligned.m16n8k8.row.col.f32.tf32.tf32.f32 "
        "{%0,%1,%2,%3}, {%4,%5,%6,%7}, {%8,%9}, {%0,%1,%2,%3};\n"
        : "+f"(c[0]), "+f"(c[1]), "+f"(c[2]), "+f"(c[3])
        : "r"(a[0]), "r"(a[1]), "r"(a[2]), "r"(a[3]), "r"(b0), "r"(b1));
}

// ---------------- prep: w2 -> tf32 bits in m16n8k8 B-fragment order ----------------
__global__ void prep_w2_kernel(const float* __restrict__ w2) {
    int idx = blockIdx.x * blockDim.x + threadIdx.x;   // 32768 threads
    if (idx >= 32 * 32 * 32) return;
    const int lane = idx & 31;
    const int nt   = (idx >> 5) & 31;     // global n-tile 0..31
    const int ks   = idx >> 10;           // k8 step 0..31
    const int n    = nt * 8 + (lane >> 2);
    const int k0   = ks * 8 + (lane & 3);
    const int wc   = nt >> 2;
    const int j    = nt & 3;
    const uint32_t pos = (uint32_t)(((ks * 8 + wc) * 32 + lane) * 8 + j * 2);

    g_w2f[pos]     = f2tf32(w2[(size_t)k0 * D + n]);          // b0: k = k0
    g_w2f[pos + 1] = f2tf32(w2[(size_t)(k0 + 4) * D + n]);    // b1: k = k0+4
}

// ---------------- main fused kernel ----------------
// A fragments in smem: Af[g=0..7][ks=0..31][lane=0..31] = uint4 {a0,a1,a2,a3}
//   a0=h(r0,c0) a1=h(r0+8,c0) a2=h(r0,c0+4) a3=h(r0+8,c0+4)
//   r0 = g*16 + (lane>>2), c0 = ks*8 + (lane&3)
#define SPITCH 17

struct Smem {
    __align__(16) uint32_t Af[8 * 32 * 32 * 4];   // 128 KB
    float w1[SD][D];                              // 14 KB
    float stats[TM][SPITCH];                      // 8.5 KB (pitch 17: conflict-free)
    float b1[D];
    float b2[D];
};

__global__ void __launch_bounds__(THREADS, 1)
tte_mma_kernel(const int* __restrict__ y,
               const float* __restrict__ g_w1,
               const float* __restrict__ g_b1,
               const float* __restrict__ g_b2,
               float* __restrict__ out)
{
    extern __shared__ char smem_raw[];
    Smem& sm = *reinterpret_cast<Smem*>(smem_raw);

    const int tid  = threadIdx.x;
    const int lane = tid & 31;
    const int wid  = tid >> 5;          // 0..15
    const int task0 = blockIdx.x * TM;

    // ---- load w1/b1/b2 ----
    {
        float* w1f = &sm.w1[0][0];
        for (int i = tid; i < SD * D; i += THREADS) w1f[i] = g_w1[i];
        if (tid < D) { sm.b1[tid] = g_b1[tid]; sm.b2[tid] = g_b2[tid]; }
    }

    // ---- Phase 1: per-task histogram stats (warp per task, 8 tasks/warp) ----
#pragma unroll
    for (int it = 0; it < TM / 16; ++it) {
        const int tt = wid * (TM / 16) + it;
        const int4 yv = *reinterpret_cast<const int4*>(
            y + (size_t)(task0 + tt) * SLEN + lane * 4);
        int cnt[NCLS];
#pragma unroll
        for (int c = 0; c < NCLS; ++c) {
            int m = (yv.x == c) + (yv.y == c) + (yv.z == c) + (yv.w == c);
            cnt[c] = __reduce_add_sync(0xffffffffu, m);
        }
        if (lane == 0) {
            float ent = 0.0f, pmax = 0.0f;
            int   nnz = 0;
#pragma unroll
            for (int c = 0; c < NCLS; ++c) {
                float pc = (float)cnt[c] * (1.0f / (float)SLEN);
                sm.stats[tt][c] = pc;
                ent  -= pc * logf(pc + 1e-6f);
                nnz  += (cnt[c] > 0);
                pmax  = fmaxf(pmax, pc);
            }
            sm.stats[tt][10] = (float)nnz;
            sm.stats[tt][11] = ent;
            sm.stats[tt][12] = (float)SLEN;
            sm.stats[tt][13] = pmax;
        }
    }
    __syncthreads();

    // ---- Phase 2: h = gelu(stats @ w1 + b1) -> tf32 A fragments in smem ----
    // warp wid handles ksteps {2*wid, 2*wid+1}
    {
#pragma unroll
        for (int t = 0; t < 2; ++t) {
            const int ks = wid * 2 + t;
            const int c0 = ks * 8 + (lane & 3);
            const int c4 = c0 + 4;
            float wc0[SD], wc4[SD];
#pragma unroll
            for (int k = 0; k < SD; ++k) { wc0[k] = sm.w1[k][c0]; wc4[k] = sm.w1[k][c4]; }
            const float bb0 = sm.b1[c0], bb4 = sm.b1[c4];

#pragma unroll
            for (int g = 0; g < 8; ++g) {
                const int r0 = g * 16 + (lane >> 2);
                const int r1 = r0 + 8;
                float s00 = bb0, s10 = bb0, s01 = bb4, s11 = bb4;
#pragma unroll
                for (int k = 0; k < SD; ++k) {
                    const float x0 = sm.stats[r0][k];
                    const float x1 = sm.stats[r1][k];
                    s00 = fmaf(x0, wc0[k], s00);
                    s01 = fmaf(x0, wc4[k], s01);
                    s10 = fmaf(x1, wc0[k], s10);
                    s11 = fmaf(x1, wc4[k], s11);
                }
                const float g00 = 0.5f * s00 * (1.0f + erff(s00 * 0.70710678118654752f));
                const float g10 = 0.5f * s10 * (1.0f + erff(s10 * 0.70710678118654752f));
                const float g01 = 0.5f * s01 * (1.0f + erff(s01 * 0.70710678118654752f));
                const float g11 = 0.5f * s11 * (1.0f + erff(s11 * 0.70710678118654752f));
                uint4 v;
                v.x = f2tf32(g00);   // a0 (r0, c0)
                v.y = f2tf32(g10);   // a1 (r0+8, c0)
                v.z = f2tf32(g01);   // a2 (r0, c0+4)
                v.w = f2tf32(g11);   // a3 (r0+8, c0+4)
                reinterpret_cast<uint4*>(sm.Af)[(g * 32 + ks) * 32 + lane] = v;
            }
        }
    }
    __syncthreads();

    // ---- Phase 3: out = h @ w2 + b2, single tf32 pass ----
    const int hw = wid >> 3;
    const int cg = wid & 7;

    float acc[4][4][4];
#pragma unroll
    for (int mt = 0; mt < 4; ++mt)
#pragma unroll
        for (int nt = 0; nt < 4; ++nt)
#pragma unroll
            for (int q = 0; q < 4; ++q) acc[mt][nt][q] = 0.0f;

    uint32_t adr = s2u(sm.Af) + (uint32_t)(((hw * 4) * 32 * 32 + lane) * 16);
    const uint32_t mstride = 32u * 32u * 16u;   // per g (A m-tile)
    const uint4* __restrict__ bptr = reinterpret_cast<const uint4*>(g_w2f) + (cg * 32 + lane) * 2;

#pragma unroll
    for (int ks = 0; ks < 32; ++ks) {
        const uint4 bq0 = bptr[0], bq1 = bptr[1];
        bptr += BSTRIDE_U4;

        uint32_t a[4][4];
#pragma unroll
        for (int mt = 0; mt < 4; ++mt) {
            asm volatile("ld.shared.v4.b32 {%0,%1,%2,%3}, [%4];"
                         : "=r"(a[mt][0]), "=r"(a[mt][1]), "=r"(a[mt][2]), "=r"(a[mt][3])
                         : "r"(adr + mt * mstride));
        }
        adr += 512;   // 32 lanes * 16 B per ks

        const uint32_t b[4][2] = { {bq0.x, bq0.y}, {bq0.z, bq0.w}, {bq1.x, bq1.y}, {bq1.z, bq1.w} };

#pragma unroll
        for (int mt = 0; mt < 4; ++mt)
#pragma unroll
            for (int nt = 0; nt < 4; ++nt)
                mma_tf32(acc[mt][nt], a[mt], b[nt][0], b[nt][1]);
    }

    // ---- Epilogue: + b2, streaming store ----
    const int colb = cg * 32;
    const int r_in = lane >> 2;
    const int c_in = (lane & 3) * 2;
#pragma unroll
    for (int nt = 0; nt < 4; ++nt) {
        const int col = colb + nt * 8 + c_in;
        const float bb0 = sm.b2[col], bb1 = sm.b2[col + 1];
#pragma unroll
        for (int mt = 0; mt < 4; ++mt) {
            const size_t r0 = (size_t)(task0 + hw * 64 + mt * 16 + r_in);
            asm volatile("st.global.cs.v2.f32 [%0], {%1,%2};"
                         :: "l"(out + r0 * D + col),
                            "f"(acc[mt][nt][0] + bb0), "f"(acc[mt][nt][1] + bb1) : "memory");
            asm volatile("st.global.cs.v2.f32 [%0], {%1,%2};"
                         :: "l"(out + (r0 + 8) * D + col),
                            "f"(acc[mt][nt][2] + bb0), "f"(acc[mt][nt][3] + bb1) : "memory");
        }
    }
}

extern "C" void kernel_launch(void* const* d_in, const int* in_sizes, int n_in,
                              void* d_out, int out_size)
{
    (void)in_sizes; (void)n_in; (void)out_size;
    const int*   y  = (const int*)  d_in[0];
    const float* w1 = (const float*)d_in[1];
    const float* b1 = (const float*)d_in[2];
    const float* w2 = (const float*)d_in[3];
    const float* b2 = (const float*)d_in[4];
    float* out = (float*)d_out;

    prep_w2_kernel<<<128, 256>>>(w2);

    const int smem = (int)sizeof(Smem);
    cudaFuncSetAttribute(tte_mma_kernel,
                         cudaFuncAttributeMaxDynamicSharedMemorySize, smem);
    tte_mma_kernel<<<BATCH / TM, THREADS, smem>>>(y, w1, b1, b2, out);
}

// round 15
// speedup vs baseline: 1.1788x; 1.1788x over previous
#include <cuda_runtime.h>
#include <cuda_bf16.h>
#include <cstdint>

#define BATCH   65536
#define SLEN    128
#define NCLS    10
#define SD      14
#define D       256
#define TM      128     // tasks per block (GEMM M)
#define THREADS 512

// w2 tf32 bits, packed in mma.m16n8k8 B-fragment order:
// uint32 index = ((ks*8 + wc)*32 + lane)*8 + j*2 + r   (verified in R14)
__device__ __align__(16) uint32_t g_w2f[32 * 8 * 32 * 8];

#define BSTRIDE_U4 512   // uint4 elements per ks step

__device__ __forceinline__ uint32_t s2u(const void* p) {
    return (uint32_t)__cvta_generic_to_shared(p);
}

__device__ __forceinline__ uint32_t f2tf32(float x) {
    uint32_t r;
    asm("cvt.rna.tf32.f32 %0, %1;" : "=r"(r) : "f"(x));
    return r;
}

__device__ __forceinline__ void mma_tf32(float* c, const uint32_t* a, uint32_t b0, uint32_t b1) {
    asm volatile(
        "mma.sync.aligned.m16n8k8.row.col.f32.tf32.tf32.f32 "
        "{%0,%1,%2,%3}, {%4,%5,%6,%7}, {%8,%9}, {%0,%1,%2,%3};\n"
        : "+f"(c[0]), "+f"(c[1]), "+f"(c[2]), "+f"(c[3])
        : "r"(a[0]), "r"(a[1]), "r"(a[2]), "r"(a[3]), "r"(b0), "r"(b1));
}

// ---------------- prep: w2 -> tf32 bits in m16n8k8 B-fragment order ----------------
__global__ void prep_w2_kernel(const float* __restrict__ w2) {
    int idx = blockIdx.x * blockDim.x + threadIdx.x;   // 32768 threads
    if (idx >= 32 * 32 * 32) return;
    const int lane = idx & 31;
    const int nt   = (idx >> 5) & 31;     // global n-tile 0..31
    const int ks   = idx >> 10;           // k8 step 0..31
    const int n    = nt * 8 + (lane >> 2);
    const int k0   = ks * 8 + (lane & 3);
    const int wc   = nt >> 2;
    const int j    = nt & 3;
    const uint32_t pos = (uint32_t)(((ks * 8 + wc) * 32 + lane) * 8 + j * 2);

    g_w2f[pos]     = f2tf32(w2[(size_t)k0 * D + n]);          // b0: k = k0
    g_w2f[pos + 1] = f2tf32(w2[(size_t)(k0 + 4) * D + n]);    // b1: k = k0+4
}

// ---------------- main fused kernel ----------------
#define HPITCH 260   // floats; 260 mod 32 == 4 -> conflict-free fragment gather
#define SPITCH 17

struct Smem {
    __align__(16) float h[TM][HPITCH];   // 133 KB, fp32 hidden activations
    float w1[SD][D];                     // 14 KB
    float stats[TM][SPITCH];             // 8.7 KB
    float b1[D];
    float b2[D];
};

__global__ void __launch_bounds__(THREADS, 1)
tte_mma_kernel(const int* __restrict__ y,
               const float* __restrict__ g_w1,
               const float* __restrict__ g_b1,
               const float* __restrict__ g_b2,
               float* __restrict__ out)
{
    extern __shared__ char smem_raw[];
    Smem& sm = *reinterpret_cast<Smem*>(smem_raw);

    const int tid  = threadIdx.x;
    const int lane = tid & 31;
    const int wid  = tid >> 5;          // 0..15
    const int task0 = blockIdx.x * TM;

    // ---- load w1/b1/b2 ----
    {
        float* w1f = &sm.w1[0][0];
        for (int i = tid; i < SD * D; i += THREADS) w1f[i] = g_w1[i];
        if (tid < D) { sm.b1[tid] = g_b1[tid]; sm.b2[tid] = g_b2[tid]; }
    }

    // ---- Phase 1: per-task histogram stats (warp per task, 8 tasks/warp) ----
#pragma unroll
    for (int it = 0; it < TM / 16; ++it) {
        const int tt = wid * (TM / 16) + it;
        const int4 yv = *reinterpret_cast<const int4*>(
            y + (size_t)(task0 + tt) * SLEN + lane * 4);
        int cnt[NCLS];
#pragma unroll
        for (int c = 0; c < NCLS; ++c) {
            int m = (yv.x == c) + (yv.y == c) + (yv.z == c) + (yv.w == c);
            cnt[c] = __reduce_add_sync(0xffffffffu, m);
        }
        if (lane == 0) {
            float ent = 0.0f, pmax = 0.0f;
            int   nnz = 0;
#pragma unroll
            for (int c = 0; c < NCLS; ++c) {
                float pc = (float)cnt[c] * (1.0f / (float)SLEN);
                sm.stats[tt][c] = pc;
                ent  -= pc * logf(pc + 1e-6f);
                nnz  += (cnt[c] > 0);
                pmax  = fmaxf(pmax, pc);
            }
            sm.stats[tt][10] = (float)nnz;
            sm.stats[tt][11] = ent;
            sm.stats[tt][12] = (float)SLEN;
            sm.stats[tt][13] = pmax;
        }
    }
    __syncthreads();

    // ---- Phase 2: h = gelu(stats @ w1 + b1) -> fp32 linear smem image ----
    // 16 warps: warp owns rows [wid*8,+8), lane owns cols [lane*8,+8)  (R12 shape)
    {
        const int ty = wid;
        const int tx = lane;
        float acc[8][8];
#pragma unroll
        for (int i = 0; i < 8; ++i)
#pragma unroll
            for (int j = 0; j < 8; ++j) acc[i][j] = sm.b1[tx * 8 + j];
#pragma unroll
        for (int k = 0; k < SD; ++k) {
            float a[8], b[8];
#pragma unroll
            for (int i = 0; i < 8; ++i) a[i] = sm.stats[ty * 8 + i][k];
#pragma unroll
            for (int j = 0; j < 8; ++j) b[j] = sm.w1[k][tx * 8 + j];
#pragma unroll
            for (int i = 0; i < 8; ++i)
#pragma unroll
                for (int j = 0; j < 8; ++j) acc[i][j] = fmaf(a[i], b[j], acc[i][j]);
        }
#pragma unroll
        for (int i = 0; i < 8; ++i) {
            const int m = ty * 8 + i;
            float4 v0, v1;
            float g0 = acc[i][0], g1 = acc[i][1], g2 = acc[i][2], g3 = acc[i][3];
            float g4 = acc[i][4], g5 = acc[i][5], g6 = acc[i][6], g7 = acc[i][7];
            v0.x = 0.5f * g0 * (1.0f + erff(g0 * 0.70710678118654752f));
            v0.y = 0.5f * g1 * (1.0f + erff(g1 * 0.70710678118654752f));
            v0.z = 0.5f * g2 * (1.0f + erff(g2 * 0.70710678118654752f));
            v0.w = 0.5f * g3 * (1.0f + erff(g3 * 0.70710678118654752f));
            v1.x = 0.5f * g4 * (1.0f + erff(g4 * 0.70710678118654752f));
            v1.y = 0.5f * g5 * (1.0f + erff(g5 * 0.70710678118654752f));
            v1.z = 0.5f * g6 * (1.0f + erff(g6 * 0.70710678118654752f));
            v1.w = 0.5f * g7 * (1.0f + erff(g7 * 0.70710678118654752f));
            *reinterpret_cast<float4*>(&sm.h[m][tx * 8])     = v0;
            *reinterpret_cast<float4*>(&sm.h[m][tx * 8 + 4]) = v1;
        }
    }
    __syncthreads();

    // ---- Phase 3: out = h @ w2 + b2, single tf32 pass, A gathered from linear h ----
    // 16 warps: hw = wid>>3 -> rows [hw*64,+64); cg = wid&7 -> cols [cg*32,+32)
    const int hw = wid >> 3;
    const int cg = wid & 7;
    const int q  = lane >> 2;   // fragment row-in-8
    const int s  = lane & 3;    // fragment col-in-4

    float acc[4][4][4];
#pragma unroll
    for (int mt = 0; mt < 4; ++mt)
#pragma unroll
        for (int nt = 0; nt < 4; ++nt)
#pragma unroll
            for (int qq = 0; qq < 4; ++qq) acc[mt][nt][qq] = 0.0f;

    // A gather base: element (g*16+q, ks*8+s); g = hw*4+mt
    uint32_t adr = s2u(sm.h) + (uint32_t)(((hw * 64 + q) * HPITCH + s) * 4);
    const uint32_t mstride = 16u * HPITCH * 4u;    // +16 rows
    const uint32_t rstride = 8u * HPITCH * 4u;     // +8 rows (a1/a3)
    const uint4* __restrict__ bptr = reinterpret_cast<const uint4*>(g_w2f) + (cg * 32 + lane) * 2;

#pragma unroll
    for (int ks = 0; ks < 32; ++ks) {
        const uint4 bq0 = bptr[0], bq1 = bptr[1];
        bptr += BSTRIDE_U4;

        uint32_t a[4][4];
#pragma unroll
        for (int mt = 0; mt < 4; ++mt) {
            const uint32_t base = adr + mt * mstride;
            float f0, f1, f2, f3;
            asm volatile("ld.shared.f32 %0, [%1];"       : "=f"(f0) : "r"(base));
            asm volatile("ld.shared.f32 %0, [%1];"       : "=f"(f1) : "r"(base + rstride));
            asm volatile("ld.shared.f32 %0, [%1];"       : "=f"(f2) : "r"(base + 16u));
            asm volatile("ld.shared.f32 %0, [%1];"       : "=f"(f3) : "r"(base + rstride + 16u));
            a[mt][0] = f2tf32(f0);   // (r0, c0)
            a[mt][1] = f2tf32(f1);   // (r0+8, c0)
            a[mt][2] = f2tf32(f2);   // (r0, c0+4)
            a[mt][3] = f2tf32(f3);   // (r0+8, c0+4)
        }
        adr += 32;   // +8 cols per ks

        const uint32_t b[4][2] = { {bq0.x, bq0.y}, {bq0.z, bq0.w}, {bq1.x, bq1.y}, {bq1.z, bq1.w} };

#pragma unroll
        for (int mt = 0; mt < 4; ++mt)
#pragma unroll
            for (int nt = 0; nt < 4; ++nt)
                mma_tf32(acc[mt][nt], a[mt], b[nt][0], b[nt][1]);
    }

    // ---- Epilogue: + b2, streaming store ----
    const int colb = cg * 32;
    const int r_in = lane >> 2;
    const int c_in = (lane & 3) * 2;
#pragma unroll
    for (int nt = 0; nt < 4; ++nt) {
        const int col = colb + nt * 8 + c_in;
        const float bb0 = sm.b2[col], bb1 = sm.b2[col + 1];
#pragma unroll
        for (int mt = 0; mt < 4; ++mt) {
            const size_t r0 = (size_t)(task0 + hw * 64 + mt * 16 + r_in);
            asm volatile("st.global.cs.v2.f32 [%0], {%1,%2};"
                         :: "l"(out + r0 * D + col),
                            "f"(acc[mt][nt][0] + bb0), "f"(acc[mt][nt][1] + bb1) : "memory");
            asm volatile("st.global.cs.v2.f32 [%0], {%1,%2};"
                         :: "l"(out + (r0 + 8) * D + col),
                            "f"(acc[mt][nt][2] + bb0), "f"(acc[mt][nt][3] + bb1) : "memory");
        }
    }
}

extern "C" void kernel_launch(void* const* d_in, const int* in_sizes, int n_in,
                              void* d_out, int out_size)
{
    (void)in_sizes; (void)n_in; (void)out_size;
    const int*   y  = (const int*)  d_in[0];
    const float* w1 = (const float*)d_in[1];
    const float* b1 = (const float*)d_in[2];
    const float* w2 = (const float*)d_in[3];
    const float* b2 = (const float*)d_in[4];
    float* out = (float*)d_out;

    prep_w2_kernel<<<128, 256>>>(w2);

    const int smem = (int)sizeof(Smem);
    cudaFuncSetAttribute(tte_mma_kernel,
                         cudaFuncAttributeMaxDynamicSharedMemorySize, smem);
    tte_mma_kernel<<<BATCH / TM, THREADS, smem>>>(y, w1, b1, b2, out);
}

// round 16
// speedup vs baseline: 1.2538x; 1.0636x over previous
#include <cuda_runtime.h>
#include <cuda_bf16.h>
#include <cstdint>

#define BATCH   65536
#define SLEN    128
#define NCLS    10
#define SD      14
#define D       256
#define TM      128     // tasks per block (GEMM M)
#define THREADS 512

// w2 tf32 bits, packed in mma.m16n8k8 B-fragment order:
// uint32 index = ((ks*8 + wc)*32 + lane)*8 + j*2 + r   (verified in R14)
__device__ __align__(16) uint32_t g_w2f[32 * 8 * 32 * 8];

#define BSTRIDE_U4 512   // uint4 elements per ks step

__device__ __forceinline__ uint32_t s2u(const void* p) {
    return (uint32_t)__cvta_generic_to_shared(p);
}

__device__ __forceinline__ uint32_t f2tf32(float x) {
    uint32_t r;
    asm("cvt.rna.tf32.f32 %0, %1;" : "=r"(r) : "f"(x));
    return r;
}

__device__ __forceinline__ void mma_tf32(float* c, const uint32_t* a, uint32_t b0, uint32_t b1) {
    asm volatile(
        "mma.sync.aligned.m16n8k8.row.col.f32.tf32.tf32.f32 "
        "{%0,%1,%2,%3}, {%4,%5,%6,%7}, {%8,%9}, {%0,%1,%2,%3};\n"
        : "+f"(c[0]), "+f"(c[1]), "+f"(c[2]), "+f"(c[3])
        : "r"(a[0]), "r"(a[1]), "r"(a[2]), "r"(a[3]), "r"(b0), "r"(b1));
}

// ---------------- prep: w2 -> tf32 bits in m16n8k8 B-fragment order ----------------
__global__ void prep_w2_kernel(const float* __restrict__ w2) {
    int idx = blockIdx.x * blockDim.x + threadIdx.x;   // 32768 threads
    if (idx >= 32 * 32 * 32) return;
    const int lane = idx & 31;
    const int nt   = (idx >> 5) & 31;     // global n-tile 0..31
    const int ks   = idx >> 10;           // k8 step 0..31
    const int n    = nt * 8 + (lane >> 2);
    const int k0   = ks * 8 + (lane & 3);
    const int wc   = nt >> 2;
    const int j    = nt & 3;
    const uint32_t pos = (uint32_t)(((ks * 8 + wc) * 32 + lane) * 8 + j * 2);

    g_w2f[pos]     = f2tf32(w2[(size_t)k0 * D + n]);          // b0: k = k0
    g_w2f[pos + 1] = f2tf32(w2[(size_t)(k0 + 4) * D + n]);    // b1: k = k0+4
}

// ---------------- main fused kernel ----------------
#define HPITCH 260   // floats; 260 mod 32 == 4 -> conflict-free fragment gather
#define SPITCH 17

struct Smem {
    __align__(16) float h[TM][HPITCH];   // 133 KB, tf32-rounded bits stored as float
    float w1[SD][D];                     // 14 KB
    float stats[TM][SPITCH];             // 8.7 KB
    float b1[D];
    float b2[D];
};

__global__ void __launch_bounds__(THREADS, 1)
tte_mma_kernel(const int* __restrict__ y,
               const float* __restrict__ g_w1,
               const float* __restrict__ g_b1,
               const float* __restrict__ g_b2,
               float* __restrict__ out)
{
    extern __shared__ char smem_raw[];
    Smem& sm = *reinterpret_cast<Smem*>(smem_raw);

    const int tid  = threadIdx.x;
    const int lane = tid & 31;
    const int wid  = tid >> 5;          // 0..15
    const int task0 = blockIdx.x * TM;

    // ---- load w1/b1/b2 ----
    {
        float* w1f = &sm.w1[0][0];
        for (int i = tid; i < SD * D; i += THREADS) w1f[i] = g_w1[i];
        if (tid < D) { sm.b1[tid] = g_b1[tid]; sm.b2[tid] = g_b2[tid]; }
    }

    // ---- Phase 1: per-task histogram stats (warp per task, 8 tasks/warp) ----
#pragma unroll
    for (int it = 0; it < TM / 16; ++it) {
        const int tt = wid * (TM / 16) + it;
        const int4 yv = *reinterpret_cast<const int4*>(
            y + (size_t)(task0 + tt) * SLEN + lane * 4);
        int cnt[NCLS];
#pragma unroll
        for (int c = 0; c < NCLS; ++c) {
            int m = (yv.x == c) + (yv.y == c) + (yv.z == c) + (yv.w == c);
            cnt[c] = __reduce_add_sync(0xffffffffu, m);
        }
        if (lane == 0) {
            float ent = 0.0f, pmax = 0.0f;
            int   nnz = 0;
#pragma unroll
            for (int c = 0; c < NCLS; ++c) {
                float pc = (float)cnt[c] * (1.0f / (float)SLEN);
                sm.stats[tt][c] = pc;
                ent  -= pc * logf(pc + 1e-6f);
                nnz  += (cnt[c] > 0);
                pmax  = fmaxf(pmax, pc);
            }
            sm.stats[tt][10] = (float)nnz;
            sm.stats[tt][11] = ent;
            sm.stats[tt][12] = (float)SLEN;
            sm.stats[tt][13] = pmax;
        }
    }
    __syncthreads();

    // ---- Phase 2: h = gelu(stats @ w1 + b1), tf32-rounded at the producer ----
    // 16 warps: warp owns rows [wid*8,+8), lane owns cols [lane*8,+8)
    {
        const int ty = wid;
        const int tx = lane;
        float acc[8][8];
#pragma unroll
        for (int i = 0; i < 8; ++i)
#pragma unroll
            for (int j = 0; j < 8; ++j) acc[i][j] = sm.b1[tx * 8 + j];
#pragma unroll
        for (int k = 0; k < SD; ++k) {
            float a[8], b[8];
#pragma unroll
            for (int i = 0; i < 8; ++i) a[i] = sm.stats[ty * 8 + i][k];
#pragma unroll
            for (int j = 0; j < 8; ++j) b[j] = sm.w1[k][tx * 8 + j];
#pragma unroll
            for (int i = 0; i < 8; ++i)
#pragma unroll
                for (int j = 0; j < 8; ++j) acc[i][j] = fmaf(a[i], b[j], acc[i][j]);
        }
#pragma unroll
        for (int i = 0; i < 8; ++i) {
            const int m = ty * 8 + i;
            uint4 v0, v1;
            float g0 = acc[i][0], g1 = acc[i][1], g2 = acc[i][2], g3 = acc[i][3];
            float g4 = acc[i][4], g5 = acc[i][5], g6 = acc[i][6], g7 = acc[i][7];
            v0.x = f2tf32(0.5f * g0 * (1.0f + erff(g0 * 0.70710678118654752f)));
            v0.y = f2tf32(0.5f * g1 * (1.0f + erff(g1 * 0.70710678118654752f)));
            v0.z = f2tf32(0.5f * g2 * (1.0f + erff(g2 * 0.70710678118654752f)));
            v0.w = f2tf32(0.5f * g3 * (1.0f + erff(g3 * 0.70710678118654752f)));
            v1.x = f2tf32(0.5f * g4 * (1.0f + erff(g4 * 0.70710678118654752f)));
            v1.y = f2tf32(0.5f * g5 * (1.0f + erff(g5 * 0.70710678118654752f)));
            v1.z = f2tf32(0.5f * g6 * (1.0f + erff(g6 * 0.70710678118654752f)));
            v1.w = f2tf32(0.5f * g7 * (1.0f + erff(g7 * 0.70710678118654752f)));
            *reinterpret_cast<uint4*>(&sm.h[m][tx * 8])     = v0;
            *reinterpret_cast<uint4*>(&sm.h[m][tx * 8 + 4]) = v1;
        }
    }
    __syncthreads();

    // ---- Phase 3: out = h @ w2 + b2, single tf32 pass, raw-bit A gather (no cvt) ----
    // 16 warps: hw = wid>>3 -> rows [hw*64,+64); cg = wid&7 -> cols [cg*32,+32)
    const int hw = wid >> 3;
    const int cg = wid & 7;
    const int q  = lane >> 2;   // fragment row-in-8
    const int s  = lane & 3;    // fragment col-in-4

    float acc[4][4][4];
#pragma unroll
    for (int mt = 0; mt < 4; ++mt)
#pragma unroll
        for (int nt = 0; nt < 4; ++nt)
#pragma unroll
            for (int qq = 0; qq < 4; ++qq) acc[mt][nt][qq] = 0.0f;

    // A gather base: element (g*16+q, ks*8+s); g = hw*4+mt
    uint32_t adr = s2u(sm.h) + (uint32_t)(((hw * 64 + q) * HPITCH + s) * 4);
    const uint32_t mstride = 16u * HPITCH * 4u;    // +16 rows
    const uint32_t rstride = 8u * HPITCH * 4u;     // +8 rows (a1/a3)
    const uint4* __restrict__ bptr = reinterpret_cast<const uint4*>(g_w2f) + (cg * 32 + lane) * 2;

#pragma unroll
    for (int ks = 0; ks < 32; ++ks) {
        const uint4 bq0 = bptr[0], bq1 = bptr[1];
        bptr += BSTRIDE_U4;

        uint32_t a[4][4];
#pragma unroll
        for (int mt = 0; mt < 4; ++mt) {
            const uint32_t base = adr + mt * mstride;
            asm volatile("ld.shared.b32 %0, [%1];" : "=r"(a[mt][0]) : "r"(base));
            asm volatile("ld.shared.b32 %0, [%1];" : "=r"(a[mt][1]) : "r"(base + rstride));
            asm volatile("ld.shared.b32 %0, [%1];" : "=r"(a[mt][2]) : "r"(base + 16u));
            asm volatile("ld.shared.b32 %0, [%1];" : "=r"(a[mt][3]) : "r"(base + rstride + 16u));
        }
        adr += 32;   // +8 cols per ks

        const uint32_t b[4][2] = { {bq0.x, bq0.y}, {bq0.z, bq0.w}, {bq1.x, bq1.y}, {bq1.z, bq1.w} };

#pragma unroll
        for (int mt = 0; mt < 4; ++mt)
#pragma unroll
            for (int nt = 0; nt < 4; ++nt)
                mma_tf32(acc[mt][nt], a[mt], b[nt][0], b[nt][1]);
    }

    // ---- Epilogue: + b2, streaming store ----
    const int colb = cg * 32;
    const int r_in = lane >> 2;
    const int c_in = (lane & 3) * 2;
#pragma unroll
    for (int nt = 0; nt < 4; ++nt) {
        const int col = colb + nt * 8 + c_in;
        const float bb0 = sm.b2[col], bb1 = sm.b2[col + 1];
#pragma unroll
        for (int mt = 0; mt < 4; ++mt) {
            const size_t r0 = (size_t)(task0 + hw * 64 + mt * 16 + r_in);
            asm volatile("st.global.cs.v2.f32 [%0], {%1,%2};"
                         :: "l"(out + r0 * D + col),
                            "f"(acc[mt][nt][0] + bb0), "f"(acc[mt][nt][1] + bb1) : "memory");
            asm volatile("st.global.cs.v2.f32 [%0], {%1,%2};"
                         :: "l"(out + (r0 + 8) * D + col),
                            "f"(acc[mt][nt][2] + bb0), "f"(acc[mt][nt][3] + bb1) : "memory");
        }
    }
}

extern "C" void kernel_launch(void* const* d_in, const int* in_sizes, int n_in,
                              void* d_out, int out_size)
{
    (void)in_sizes; (void)n_in; (void)out_size;
    const int*   y  = (const int*)  d_in[0];
    const float* w1 = (const float*)d_in[1];
    const float* b1 = (const float*)d_in[2];
    const float* w2 = (const float*)d_in[3];
    const float* b2 = (const float*)d_in[4];
    float* out = (float*)d_out;

    prep_w2_kernel<<<128, 256>>>(w2);

    const int smem = (int)sizeof(Smem);
    cudaFuncSetAttribute(tte_mma_kernel,
                         cudaFuncAttributeMaxDynamicSharedMemorySize, smem);
    tte_mma_kernel<<<BATCH / TM, THREADS, smem>>>(y, w1, b1, b2, out);
}